// round 14
// baseline (speedup 1.0000x reference)
#include <cuda_runtime.h>
#include <math.h>

#define BATCH 2
#define NPTS  4096
#define MQ    4096
#define NQ    (BATCH * MQ)

// scratch
__device__ float  g_f1[NQ * 128];
__device__ float  g_f2[NQ * 128];
__device__ float4 g_p4[BATCH * NPTS];   // (x, y, z, 0) packed points
__device__ float  g_W3t[256 * 128];     // transposed final weights [c][o]
__device__ float  g_geo[2 * NQ * 192];  // per scale, per query: la[64] lb[64] pz[64]
__device__ int    g_cnt[2 * NQ];        // send counts (even)

// ---------------- f32x2 helpers ----------------
typedef unsigned long long u64;
__device__ __forceinline__ u64 pack2(float x) {
    u64 r; asm("mov.b64 %0, {%1,%1};" : "=l"(r) : "f"(x)); return r;
}
__device__ __forceinline__ u64 pack2(float x, float y) {
    u64 r; asm("mov.b64 %0, {%1,%2};" : "=l"(r) : "f"(x), "f"(y)); return r;
}
__device__ __forceinline__ void unpack2(u64 v, float& x, float& y) {
    asm("mov.b64 {%0,%1}, %2;" : "=f"(x), "=f"(y) : "l"(v));
}
__device__ __forceinline__ void ffma2(u64& d, u64 a, u64 b) {
    asm("fma.rn.f32x2 %0, %1, %2, %0;" : "+l"(d) : "l"(a), "l"(b));
}
__device__ __forceinline__ u64 ffma2c(u64 a, u64 b, u64 c) {
    u64 d; asm("fma.rn.f32x2 %0, %1, %2, %3;" : "=l"(d) : "l"(a), "l"(b), "l"(c)); return d;
}
__device__ __forceinline__ u64 relu2(u64 v) {
    float x, y; unpack2(v, x, y);
    return pack2(fmaxf(x, 0.f), fmaxf(y, 0.f));
}

// =============== prep: pack points to float4 + transpose final weights ===============
__global__ void prep_kernel(const float* __restrict__ pts, const float* __restrict__ w3)
{
    int i = blockIdx.x * blockDim.x + threadIdx.x;   // 0..32767
    if (i < BATCH * NPTS) {
        float x = pts[i * 3 + 0], y = pts[i * 3 + 1], z = pts[i * 3 + 2];
        g_p4[i] = make_float4(x, y, z, 0.0f);
    }
    if (i < 128 * 256) {
        int o = i >> 8, c = i & 255;
        g_W3t[c * 128 + o] = w3[i];
    }
}

// =============== geometry kernel: ball query + LRF (low smem, high occ) ===============
__global__ void __launch_bounds__(256)
geom_kernel()
{
    __shared__ float sm[8][352];
    const int tid  = threadIdx.x;
    const int lane = tid & 31;
    const int wid  = tid >> 5;
    float* wr   = sm[wid];
    float* relx = wr;        float* rely = wr + 64;  float* relz = wr + 128;
    float* wgt  = wr + 192;  float* pzv  = wr + 256; float* msc  = wr + 320;

    const bool sc2 = blockIdx.x < 1024;
    const float radius = sc2 ? 0.2f : 0.1f;
    const int   NS     = sc2 ? 64 : 32;
    const int   goff   = sc2 ? 0 : NQ * 192;
    const int   coff   = sc2 ? 0 : NQ;

    const int qi = (blockIdx.x & 1023) * 8 + wid;
    const int b  = qi >> 12;
    const int m  = qi & (MQ - 1);
    const float4* p4 = g_p4 + b * NPTS;
    const float4 q4 = p4[m];
    const float qx = q4.x, qy = q4.y, qz = q4.z;
    const float r2 = radius * radius;
    const unsigned lmask = (1u << lane) - 1u;

    // warp-synchronous ball query: 64 points per iteration (2 float4 per lane)
    int cnt = 0;
    for (int c = 0; c < NPTS && cnt < NS; c += 64) {
        int i0 = c + 2 * lane;
        float4 p0 = p4[i0], p1 = p4[i0 + 1];
        float dx0 = p0.x - qx, dy0 = p0.y - qy, dz0 = p0.z - qz;
        float dx1 = p1.x - qx, dy1 = p1.y - qy, dz1 = p1.z - qz;
        float d20 = dx0 * dx0 + dy0 * dy0 + dz0 * dz0;
        float d21 = dx1 * dx1 + dy1 * dy1 + dz1 * dz1;
        bool pr0 = d20 < r2, pr1 = d21 < r2;
        unsigned b0 = __ballot_sync(0xffffffffu, pr0);
        unsigned b1 = __ballot_sync(0xffffffffu, pr1);
        int before = cnt + __popc(b0 & lmask) + __popc(b1 & lmask);
        int pos0 = before;
        int pos1 = before + (pr0 ? 1 : 0);
        if (pr0 && pos0 < NS) {
            relx[pos0] = dx0; rely[pos0] = dy0; relz[pos0] = dz0;
            wgt[pos0]  = fmaxf(radius - sqrtf(d20), 0.0f);
        }
        if (pr1 && pos1 < NS) {
            relx[pos1] = dx1; rely[pos1] = dy1; relz[pos1] = dz1;
            wgt[pos1]  = fmaxf(radius - sqrtf(d21), 0.0f);
        }
        cnt += __popc(b0) + __popc(b1);
    }
    cnt = min(cnt, NS);
    __syncwarp();
    // pair-granularity padding: duplicates beyond cnt cannot change max-pool
    const int send = min(NS, (cnt + 1) & ~1);
    {
        float r0x = relx[0], r0y = rely[0], r0z = relz[0], w0 = wgt[0];
        for (int i = cnt + lane; i < send; i += 32) {
            relx[i] = r0x; rely[i] = r0y; relz[i] = r0z; wgt[i] = w0;
        }
    }
    __syncwarp();

    // weighted covariance + Σrel (fp64 warp reduce)
    {
        double acc[10];
        #pragma unroll
        for (int i = 0; i < 10; i++) acc[i] = 0.0;
        for (int si = lane; si < NS; si += 32) {
            int j = (si < cnt) ? si : 0;    // replicate-first semantics
            double rx = relx[j], ry = rely[j], rz = relz[j], w = wgt[j];
            acc[0] += w * rx * rx; acc[1] += w * rx * ry; acc[2] += w * rx * rz;
            acc[3] += w * ry * ry; acc[4] += w * ry * rz; acc[5] += w * rz * rz;
            acc[6] += w; acc[7] += rx; acc[8] += ry; acc[9] += rz;
        }
        #pragma unroll
        for (int off = 16; off; off >>= 1) {
            #pragma unroll
            for (int i = 0; i < 10; i++) acc[i] += __shfl_down_sync(0xffffffffu, acc[i], off);
        }
        if (lane == 0) {
            double inv = 1.0 / (acc[6] + 1e-8);
            double a00 = acc[0] * inv, a01 = acc[1] * inv, a02 = acc[2] * inv;
            double a11 = acc[3] * inv, a12 = acc[4] * inv, a22 = acc[5] * inv;
            double zx, zy, zz;
            double p1 = a01 * a01 + a02 * a02 + a12 * a12;
            if (p1 < 1e-30) {
                if (a00 <= a11 && a00 <= a22)      { zx = 1; zy = 0; zz = 0; }
                else if (a11 <= a22)               { zx = 0; zy = 1; zz = 0; }
                else                               { zx = 0; zy = 0; zz = 1; }
            } else {
                double q  = (a00 + a11 + a22) / 3.0;
                double b00 = a00 - q, b11 = a11 - q, b22 = a22 - q;
                double p2 = b00 * b00 + b11 * b11 + b22 * b22 + 2.0 * p1;
                double p  = sqrt(p2 / 6.0);
                double ip = 1.0 / p;
                double c00 = b00 * ip, c01 = a01 * ip, c02 = a02 * ip;
                double c11 = b11 * ip, c12 = a12 * ip, c22 = b22 * ip;
                double detB = c00 * (c11 * c22 - c12 * c12)
                            - c01 * (c01 * c22 - c12 * c02)
                            + c02 * (c01 * c12 - c11 * c02);
                double r = fmin(1.0, fmax(-1.0, 0.5 * detB));
                double phi = acos(r) / 3.0;
                double lmin = q + 2.0 * p * cos(phi + 2.0943951023931953);
                double r0x = a00 - lmin, r0y = a01,        r0z = a02;
                double r1x = a01,        r1y = a11 - lmin, r1z = a12;
                double r2x = a02,        r2y = a12,        r2z = a22 - lmin;
                double v0x = r0y * r1z - r0z * r1y, v0y = r0z * r1x - r0x * r1z, v0z = r0x * r1y - r0y * r1x;
                double v1x = r0y * r2z - r0z * r2y, v1y = r0z * r2x - r0x * r2z, v1z = r0x * r2y - r0y * r2x;
                double v2x = r1y * r2z - r1z * r2y, v2y = r1z * r2x - r1x * r2z, v2z = r1x * r2y - r1y * r2x;
                double n0 = v0x * v0x + v0y * v0y + v0z * v0z;
                double n1 = v1x * v1x + v1y * v1y + v1z * v1z;
                double n2 = v2x * v2x + v2y * v2y + v2z * v2z;
                double vx, vy, vz, nn;
                if (n0 >= n1 && n0 >= n2)      { vx = v0x; vy = v0y; vz = v0z; nn = n0; }
                else if (n1 >= n2)             { vx = v1x; vy = v1y; vz = v1z; nn = n1; }
                else                           { vx = v2x; vy = v2y; vz = v2z; nn = n2; }
                double inr = (nn > 0.0) ? (1.0 / sqrt(nn)) : 0.0;
                zx = vx * inr; zy = vy * inr; zz = vz * inr;
            }
            double dotz = acc[7] * zx + acc[8] * zy + acc[9] * zz;
            if (dotz > 0.0) { zx = -zx; zy = -zy; zz = -zz; }
            msc[0] = (float)zx; msc[1] = (float)zy; msc[2] = (float)zz;
        }
    }
    __syncwarp();

    {   // pz per neighbor
        float zx = msc[0], zy = msc[1], zz = msc[2];
        for (int i = lane; i < send; i += 32)
            pzv[i] = relx[i] * zx + rely[i] * zy + relz[i] * zz;
    }
    __syncwarp();

    {   // xv accumulation (fp64 warp reduce)
        double zx = msc[0], zy = msc[1], zz = msc[2];
        double sx = 0, sy = 0, sz = 0;
        for (int si = lane; si < NS; si += 32) {
            int j = (si < cnt) ? si : 0;
            double pzd = pzv[j], w = wgt[j];
            double t = (w * w) * (pzd * pzd);
            sx += t * (relx[j] - pzd * zx);
            sy += t * (rely[j] - pzd * zy);
            sz += t * (relz[j] - pzd * zz);
        }
        #pragma unroll
        for (int off = 16; off; off >>= 1) {
            sx += __shfl_down_sync(0xffffffffu, sx, off);
            sy += __shfl_down_sync(0xffffffffu, sy, off);
            sz += __shfl_down_sync(0xffffffffu, sz, off);
        }
        if (lane == 0) {
            double nrm = sqrt(sx * sx + sy * sy + sz * sz);
            double inr = 1.0 / (nrm + 1e-8);
            float xx = (float)(sx * inr), xy = (float)(sy * inr), xz = (float)(sz * inr);
            msc[3] = xx; msc[4] = xy; msc[5] = xz;
            float zx2 = msc[0], zy2 = msc[1], zz2 = msc[2];
            msc[6] = zy2 * xz - zz2 * xy;
            msc[7] = zz2 * xx - zx2 * xz;
            msc[8] = zx2 * xy - zy2 * xx;
        }
    }
    __syncwarp();

    {   // LRF in-plane coords -> write geometry to global
        float xx = msc[3], xy = msc[4], xz = msc[5];
        float yx = msc[6], yy = msc[7], yz = msc[8];
        float* gq = g_geo + goff + (size_t)qi * 192;
        for (int i = lane; i < send; i += 32) {
            float rx = relx[i], ry = rely[i], rz = relz[i];
            gq[i]       = rx * xx + ry * xy + rz * xz;
            gq[64 + i]  = rx * yx + ry * yy + rz * yz;
            gq[128 + i] = pzv[i];
        }
        if (lane == 0) g_cnt[coff + qi] = send;
    }
}

// =============== MLP kernel: pure f32x2 compute (big smem, 2 blocks/SM) ===============
// W3q  : float4 [64][32]   32768 B @ 0
// W2q  : float2 [32][32]    8192 B @ 32768
// h1   : u64 [8][32][10]   20480 B @ 40960
// h2   : u64 [8][64][10]   40960 B @ 61440
// geos : float [8][192]     6144 B @ 102400
#define MLP_SMEM 108544

__global__ void __launch_bounds__(256, 2)
mlp_kernel(const float* __restrict__ w1a, const float* __restrict__ g1a, const float* __restrict__ b1a,
           const float* __restrict__ w1b, const float* __restrict__ g1b, const float* __restrict__ b1b,
           const float* __restrict__ w1c, const float* __restrict__ g1c, const float* __restrict__ b1c,
           const float* __restrict__ w2a, const float* __restrict__ g2a, const float* __restrict__ b2a,
           const float* __restrict__ w2b, const float* __restrict__ g2b, const float* __restrict__ b2b,
           const float* __restrict__ w2c, const float* __restrict__ g2c, const float* __restrict__ b2c)
{
    extern __shared__ unsigned char smraw[];
    float4* W3q = (float4*)smraw;
    float2* W2q = (float2*)(smraw + 32768);
    const int tid  = threadIdx.x;
    const int lane = tid & 31;
    const int wid  = tid >> 5;
    u64*   h1w  = (u64*)(smraw + 40960 + wid * 2560);
    u64*   h2w  = (u64*)(smraw + 61440 + wid * 5120);
    float* geos = (float*)(smraw + 102400) + wid * 192;
    const float4* la4 = (const float4*)geos;          // la quads
    const float4* lb4 = (const float4*)(geos + 64);   // lb quads
    const float4* pz4 = (const float4*)(geos + 128);  // pz quads

    const bool sc2 = blockIdx.x < 1024;
    const float* W1  = sc2 ? w2a : w1a;  const float* G1 = sc2 ? g2a : g1a;  const float* B1 = sc2 ? b2a : b1a;
    const float* W2  = sc2 ? w2b : w1b;  const float* G2 = sc2 ? g2b : g1b;  const float* B2 = sc2 ? b2b : b1b;
    const float* W3L = sc2 ? w2c : w1c;  const float* G3 = sc2 ? g2c : g1c;  const float* B3 = sc2 ? b2c : b1c;
    float* fout = sc2 ? g_f2 : g_f1;
    const int goff = sc2 ? 0 : NQ * 192;
    const int coff = sc2 ? 0 : NQ;

    // stage weights
    for (int i = tid; i < 64 * 32; i += 256) {
        int k = i >> 5, l = i & 31;
        W3q[k * 32 + l] = make_float4(W3L[l * 64 + k], W3L[(l + 32) * 64 + k],
                                      W3L[(l + 64) * 64 + k], W3L[(l + 96) * 64 + k]);
    }
    for (int i = tid; i < 32 * 32; i += 256) {
        int k = i >> 5, l = i & 31;
        W2q[k * 32 + l] = make_float2(W2[l * 32 + k], W2[(l + 32) * 32 + k]);
    }

    const int qi = (blockIdx.x & 1023) * 8 + wid;
    const int send = g_cnt[coff + qi];   // even, >= 2

    // preload geometry for this query
    {
        const float* gq = g_geo + goff + (size_t)qi * 192;
        for (int i = lane; i < 192; i += 32) geos[i] = gq[i];
    }
    __syncthreads();   // weights staged (also covers geos)

    const float bns = 0.99999500003749968752f;  // 1/sqrt(1+1e-5)
    const float wa0 = W1[lane * 3 + 0], wa1 = W1[lane * 3 + 1], wa2 = W1[lane * 3 + 2];
    const float s1  = G1[lane] * bns,  b1v = B1[lane];

    float fm[4] = {0.f, 0.f, 0.f, 0.f};

    for (int s0 = 0; s0 < send; s0 += 16) {
        const int rem   = send - s0;
        const int npair = (rem >= 16) ? 8 : (rem >> 1);       // 1..8
        const int nquad = (npair + 1) >> 1;                   // 1..4
        const int q0 = s0 >> 2;                               // quad index base

        // layer 1: per-quad float4 broadcasts, STS.128 store (guarded static unroll)
        #pragma unroll
        for (int pp = 0; pp < 4; pp++) {
            if (pp < nquad) {
                float4 a = la4[q0 + pp];
                float4 bq = lb4[q0 + pp];
                float4 c = pz4[q0 + pp];
                float v0 = fmaxf(fmaf(fmaf(wa0, a.x, fmaf(wa1, bq.x, wa2 * c.x)), s1, b1v), 0.f);
                float v1 = fmaxf(fmaf(fmaf(wa0, a.y, fmaf(wa1, bq.y, wa2 * c.y)), s1, b1v), 0.f);
                float v2 = fmaxf(fmaf(fmaf(wa0, a.z, fmaf(wa1, bq.z, wa2 * c.z)), s1, b1v), 0.f);
                float v3 = fmaxf(fmaf(fmaf(wa0, a.w, fmaf(wa1, bq.w, wa2 * c.w)), s1, b1v), 0.f);
                ulonglong2 st;
                st.x = pack2(v0, v1);
                st.y = pack2(v2, v3);
                *(ulonglong2*)&h1w[lane * 10 + 2 * pp] = st;
            }
        }
        __syncwarp();

        // layer 2: 32 -> 64
        {
            u64 acc2[16];
            #pragma unroll
            for (int i = 0; i < 16; i++) acc2[i] = 0;
            if (npair == 8) {
                #pragma unroll 4
                for (int k = 0; k < 32; k++) {
                    float2 w = W2q[k * 32 + lane];
                    u64 wA = pack2(w.x), wB = pack2(w.y);
                    ulonglong2 t01 = *(const ulonglong2*)&h1w[k * 10];
                    ulonglong2 t23 = *(const ulonglong2*)&h1w[k * 10 + 2];
                    ulonglong2 t45 = *(const ulonglong2*)&h1w[k * 10 + 4];
                    ulonglong2 t67 = *(const ulonglong2*)&h1w[k * 10 + 6];
                    u64 hh[8] = {t01.x, t01.y, t23.x, t23.y, t45.x, t45.y, t67.x, t67.y};
                    #pragma unroll
                    for (int p = 0; p < 8; p++) { ffma2(acc2[p], wA, hh[p]); ffma2(acc2[8 + p], wB, hh[p]); }
                }
            } else {
                for (int k = 0; k < 32; k++) {
                    float2 w = W2q[k * 32 + lane];
                    u64 wA = pack2(w.x), wB = pack2(w.y);
                    #pragma unroll
                    for (int p = 0; p < 8; p++) {
                        if (p < npair) {
                            u64 h = h1w[k * 10 + p];
                            ffma2(acc2[p], wA, h);
                            ffma2(acc2[8 + p], wB, h);
                        }
                    }
                }
            }
            u64 sA = pack2(G2[lane] * bns),      bA = pack2(B2[lane]);
            u64 sB = pack2(G2[lane + 32] * bns), bB = pack2(B2[lane + 32]);
            #pragma unroll
            for (int pp = 0; pp < 4; pp++) {
                if (pp < nquad) {
                    ulonglong2 stA, stB;
                    stA.x = relu2(ffma2c(acc2[2 * pp],     sA, bA));
                    stA.y = relu2(ffma2c(acc2[2 * pp + 1], sA, bA));
                    stB.x = relu2(ffma2c(acc2[8 + 2 * pp],     sB, bB));
                    stB.y = relu2(ffma2c(acc2[8 + 2 * pp + 1], sB, bB));
                    *(ulonglong2*)&h2w[lane * 10 + 2 * pp] = stA;
                    *(ulonglong2*)&h2w[(lane + 32) * 10 + 2 * pp] = stB;
                }
            }
        }
        __syncwarp();

        // layer 3: 64 -> 128, single pass, 4 out-groups
        {
            u64 acc3[32];
            #pragma unroll
            for (int i = 0; i < 32; i++) acc3[i] = 0;
            if (npair == 8) {
                #pragma unroll 8
                for (int k = 0; k < 64; k++) {
                    float4 w4 = W3q[k * 32 + lane];
                    u64 wp0 = pack2(w4.x), wp1 = pack2(w4.y), wp2 = pack2(w4.z), wp3 = pack2(w4.w);
                    ulonglong2 t01 = *(const ulonglong2*)&h2w[k * 10];
                    ulonglong2 t23 = *(const ulonglong2*)&h2w[k * 10 + 2];
                    ulonglong2 t45 = *(const ulonglong2*)&h2w[k * 10 + 4];
                    ulonglong2 t67 = *(const ulonglong2*)&h2w[k * 10 + 6];
                    u64 hh[8] = {t01.x, t01.y, t23.x, t23.y, t45.x, t45.y, t67.x, t67.y};
                    #pragma unroll
                    for (int p = 0; p < 8; p++) {
                        ffma2(acc3[p],      wp0, hh[p]);
                        ffma2(acc3[8 + p],  wp1, hh[p]);
                        ffma2(acc3[16 + p], wp2, hh[p]);
                        ffma2(acc3[24 + p], wp3, hh[p]);
                    }
                }
            } else {
                for (int k = 0; k < 64; k++) {
                    float4 w4 = W3q[k * 32 + lane];
                    u64 wp0 = pack2(w4.x), wp1 = pack2(w4.y), wp2 = pack2(w4.z), wp3 = pack2(w4.w);
                    #pragma unroll
                    for (int p = 0; p < 8; p++) {
                        if (p < npair) {
                            u64 h = h2w[k * 10 + p];
                            ffma2(acc3[p],      wp0, h);
                            ffma2(acc3[8 + p],  wp1, h);
                            ffma2(acc3[16 + p], wp2, h);
                            ffma2(acc3[24 + p], wp3, h);
                        }
                    }
                }
            }
            #pragma unroll
            for (int j = 0; j < 4; j++) {
                u64 s3 = pack2(G3[lane + 32 * j] * bns), b3 = pack2(B3[lane + 32 * j]);
                #pragma unroll
                for (int p = 0; p < 8; p++) {
                    if (p < npair) {
                        u64 t = ffma2c(acc3[j * 8 + p], s3, b3);
                        float x, y; unpack2(t, x, y);
                        fm[j] = fmaxf(fm[j], fmaxf(x, y));
                    }
                }
            }
        }
        __syncwarp();
    }

    #pragma unroll
    for (int j = 0; j < 4; j++)
        fout[(size_t)qi * 128 + lane + 32 * j] = fm[j];
}

// ---------------- final linear: f32x2 query pairs, weights via LDG ----------------
#define FINAL_SMEM 65536   // fp: u64 [32 pairs][256 c]

__global__ void __launch_bounds__(512)
final_kernel(const float* __restrict__ B3f, float* __restrict__ out)
{
    extern __shared__ unsigned char fraw[];
    u64* fp = (u64*)fraw;               // [pair][256]
    const int tid = threadIdx.x, lane = tid & 31, wid = tid >> 5;
    const int q0 = blockIdx.x * 64;

    // stage packed feature pairs: fp[pr][c] = (feat[q0+2pr][c], feat[q0+2pr+1][c])
    for (int i = tid; i < 32 * 128; i += 512) {
        int pr = i >> 7, c = i & 127;
        size_t ra = (size_t)(q0 + 2 * pr) * 128 + c;
        size_t rb = (size_t)(q0 + 2 * pr + 1) * 128 + c;
        fp[pr * 256 + c]       = pack2(g_f1[ra], g_f1[rb]);
        fp[pr * 256 + 128 + c] = pack2(g_f2[ra], g_f2[rb]);
    }
    __syncthreads();

    u64 acc[2][4];   // [local pair][output group]
    #pragma unroll
    for (int pr = 0; pr < 2; pr++)
        #pragma unroll
        for (int j = 0; j < 4; j++) acc[pr][j] = 0;

    const int prbase = wid * 2;   // 2 pairs (4 queries) per warp
    #pragma unroll 8
    for (int c = 0; c < 256; c++) {
        const float* wr = g_W3t + c * 128;
        u64 wp0 = pack2(wr[lane]);
        u64 wp1 = pack2(wr[lane + 32]);
        u64 wp2 = pack2(wr[lane + 64]);
        u64 wp3 = pack2(wr[lane + 96]);
        #pragma unroll
        for (int pr = 0; pr < 2; pr++) {
            u64 f = fp[(prbase + pr) * 256 + c];
            ffma2(acc[pr][0], wp0, f);
            ffma2(acc[pr][1], wp1, f);
            ffma2(acc[pr][2], wp2, f);
            ffma2(acc[pr][3], wp3, f);
        }
    }
    #pragma unroll
    for (int pr = 0; pr < 2; pr++) {
        int qa = q0 + 2 * (prbase + pr);
        #pragma unroll
        for (int j = 0; j < 4; j++) {
            float x, y; unpack2(acc[pr][j], x, y);
            float bb = B3f[lane + 32 * j];
            out[(size_t)qa * 128 + lane + 32 * j]       = x + bb;
            out[(size_t)(qa + 1) * 128 + lane + 32 * j] = y + bb;
        }
    }
}

extern "C" void kernel_launch(void* const* d_in, const int* in_sizes, int n_in,
                              void* d_out, int out_size)
{
    const float* pts  = (const float*)d_in[0];
    const float* w1a  = (const float*)d_in[1];
    const float* g1a  = (const float*)d_in[2];
    const float* bb1a = (const float*)d_in[3];
    const float* w1b  = (const float*)d_in[4];
    const float* g1b  = (const float*)d_in[5];
    const float* bb1b = (const float*)d_in[6];
    const float* w1c  = (const float*)d_in[7];
    const float* g1c  = (const float*)d_in[8];
    const float* bb1c = (const float*)d_in[9];
    const float* w2a  = (const float*)d_in[10];
    const float* g2a  = (const float*)d_in[11];
    const float* bb2a = (const float*)d_in[12];
    const float* w2b  = (const float*)d_in[13];
    const float* g2b  = (const float*)d_in[14];
    const float* bb2b = (const float*)d_in[15];
    const float* w2c  = (const float*)d_in[16];
    const float* g2c  = (const float*)d_in[17];
    const float* bb2c = (const float*)d_in[18];
    const float* w3   = (const float*)d_in[19];
    const float* b3   = (const float*)d_in[20];

    cudaFuncSetAttribute(mlp_kernel, cudaFuncAttributeMaxDynamicSharedMemorySize, MLP_SMEM);
    cudaFuncSetAttribute(final_kernel, cudaFuncAttributeMaxDynamicSharedMemorySize, FINAL_SMEM);

    prep_kernel<<<128, 256>>>(pts, w3);
    geom_kernel<<<2048, 256>>>();
    mlp_kernel<<<2048, 256, MLP_SMEM>>>(w1a, g1a, bb1a, w1b, g1b, bb1b, w1c, g1c, bb1c,
                                        w2a, g2a, bb2a, w2b, g2b, bb2b, w2c, g2c, bb2c);
    final_kernel<<<NQ / 64, 512, FINAL_SMEM>>>(b3, (float*)d_out);
}

// round 15
// speedup vs baseline: 1.1369x; 1.1369x over previous
#include <cuda_runtime.h>
#include <math.h>

#define BATCH 2
#define NPTS  4096
#define MQ    4096
#define NQ    (BATCH * MQ)

// scratch
__device__ float  g_f1[NQ * 128];
__device__ float  g_f2[NQ * 128];
__device__ float4 g_p4[BATCH * NPTS];   // (x, y, z, 0) packed points
__device__ float  g_W3t[256 * 128];     // transposed final weights [c][o]
__device__ float  g_geo[2 * NQ * 192];  // per scale, per query: la[64] lb[64] pz[64]
__device__ int    g_cnt[2 * NQ];        // send counts

// ---------------- f32x2 helpers ----------------
typedef unsigned long long u64;
__device__ __forceinline__ u64 pack2(float x) {
    u64 r; asm("mov.b64 %0, {%1,%1};" : "=l"(r) : "f"(x)); return r;
}
__device__ __forceinline__ u64 pack2(float x, float y) {
    u64 r; asm("mov.b64 %0, {%1,%2};" : "=l"(r) : "f"(x), "f"(y)); return r;
}
__device__ __forceinline__ void unpack2(u64 v, float& x, float& y) {
    asm("mov.b64 {%0,%1}, %2;" : "=f"(x), "=f"(y) : "l"(v));
}
__device__ __forceinline__ void ffma2(u64& d, u64 a, u64 b) {
    asm("fma.rn.f32x2 %0, %1, %2, %0;" : "+l"(d) : "l"(a), "l"(b));
}
__device__ __forceinline__ u64 ffma2c(u64 a, u64 b, u64 c) {
    u64 d; asm("fma.rn.f32x2 %0, %1, %2, %3;" : "=l"(d) : "l"(a), "l"(b), "l"(c)); return d;
}
__device__ __forceinline__ u64 relu2(u64 v) {
    float x, y; unpack2(v, x, y);
    return pack2(fmaxf(x, 0.f), fmaxf(y, 0.f));
}

// =============== prep: pack points to float4 + transpose final weights ===============
__global__ void prep_kernel(const float* __restrict__ pts, const float* __restrict__ w3)
{
    int i = blockIdx.x * blockDim.x + threadIdx.x;   // 0..32767
    if (i < BATCH * NPTS) {
        float x = pts[i * 3 + 0], y = pts[i * 3 + 1], z = pts[i * 3 + 2];
        g_p4[i] = make_float4(x, y, z, 0.0f);
    }
    if (i < 128 * 256) {
        int o = i >> 8, c = i & 255;
        g_W3t[c * 128 + o] = w3[i];
    }
}

// =============== geometry kernel: ball query + LRF (low smem, high occ) ===============
__global__ void __launch_bounds__(256)
geom_kernel()
{
    __shared__ float sm[8][352];
    const int tid  = threadIdx.x;
    const int lane = tid & 31;
    const int wid  = tid >> 5;
    float* wr   = sm[wid];
    float* relx = wr;        float* rely = wr + 64;  float* relz = wr + 128;
    float* wgt  = wr + 192;  float* pzv  = wr + 256; float* msc  = wr + 320;

    const bool sc2 = blockIdx.x < 1024;
    const float radius = sc2 ? 0.2f : 0.1f;
    const int   NS     = sc2 ? 64 : 32;
    const int   goff   = sc2 ? 0 : NQ * 192;
    const int   coff   = sc2 ? 0 : NQ;

    const int qi = (blockIdx.x & 1023) * 8 + wid;
    const int b  = qi >> 12;
    const int m  = qi & (MQ - 1);
    const float4* p4 = g_p4 + b * NPTS;
    const float4 q4 = p4[m];
    const float qx = q4.x, qy = q4.y, qz = q4.z;
    const float r2 = radius * radius;
    const unsigned lmask = (1u << lane) - 1u;

    // warp-synchronous ball query: 64 points per iteration (2 float4 per lane)
    int cnt = 0;
    for (int c = 0; c < NPTS && cnt < NS; c += 64) {
        int i0 = c + 2 * lane;
        float4 p0 = p4[i0], p1 = p4[i0 + 1];
        float dx0 = p0.x - qx, dy0 = p0.y - qy, dz0 = p0.z - qz;
        float dx1 = p1.x - qx, dy1 = p1.y - qy, dz1 = p1.z - qz;
        float d20 = dx0 * dx0 + dy0 * dy0 + dz0 * dz0;
        float d21 = dx1 * dx1 + dy1 * dy1 + dz1 * dz1;
        bool pr0 = d20 < r2, pr1 = d21 < r2;
        unsigned b0 = __ballot_sync(0xffffffffu, pr0);
        unsigned b1 = __ballot_sync(0xffffffffu, pr1);
        int before = cnt + __popc(b0 & lmask) + __popc(b1 & lmask);
        int pos0 = before;
        int pos1 = before + (pr0 ? 1 : 0);
        if (pr0 && pos0 < NS) {
            relx[pos0] = dx0; rely[pos0] = dy0; relz[pos0] = dz0;
            wgt[pos0]  = fmaxf(radius - sqrtf(d20), 0.0f);
        }
        if (pr1 && pos1 < NS) {
            relx[pos1] = dx1; rely[pos1] = dy1; relz[pos1] = dz1;
            wgt[pos1]  = fmaxf(radius - sqrtf(d21), 0.0f);
        }
        cnt += __popc(b0) + __popc(b1);
    }
    cnt = min(cnt, NS);
    __syncwarp();
    const int send = min(NS, (cnt + 7) & ~7);
    {
        float r0x = relx[0], r0y = rely[0], r0z = relz[0], w0 = wgt[0];
        for (int i = cnt + lane; i < send; i += 32) {
            relx[i] = r0x; rely[i] = r0y; relz[i] = r0z; wgt[i] = w0;
        }
    }
    __syncwarp();

    // weighted covariance + Σrel (fp64 warp reduce)
    {
        double acc[10];
        #pragma unroll
        for (int i = 0; i < 10; i++) acc[i] = 0.0;
        for (int si = lane; si < NS; si += 32) {
            int j = (si < cnt) ? si : 0;    // replicate-first semantics
            double rx = relx[j], ry = rely[j], rz = relz[j], w = wgt[j];
            acc[0] += w * rx * rx; acc[1] += w * rx * ry; acc[2] += w * rx * rz;
            acc[3] += w * ry * ry; acc[4] += w * ry * rz; acc[5] += w * rz * rz;
            acc[6] += w; acc[7] += rx; acc[8] += ry; acc[9] += rz;
        }
        #pragma unroll
        for (int off = 16; off; off >>= 1) {
            #pragma unroll
            for (int i = 0; i < 10; i++) acc[i] += __shfl_down_sync(0xffffffffu, acc[i], off);
        }
        if (lane == 0) {
            double inv = 1.0 / (acc[6] + 1e-8);
            double a00 = acc[0] * inv, a01 = acc[1] * inv, a02 = acc[2] * inv;
            double a11 = acc[3] * inv, a12 = acc[4] * inv, a22 = acc[5] * inv;
            double zx, zy, zz;
            double p1 = a01 * a01 + a02 * a02 + a12 * a12;
            if (p1 < 1e-30) {
                if (a00 <= a11 && a00 <= a22)      { zx = 1; zy = 0; zz = 0; }
                else if (a11 <= a22)               { zx = 0; zy = 1; zz = 0; }
                else                               { zx = 0; zy = 0; zz = 1; }
            } else {
                double q  = (a00 + a11 + a22) / 3.0;
                double b00 = a00 - q, b11 = a11 - q, b22 = a22 - q;
                double p2 = b00 * b00 + b11 * b11 + b22 * b22 + 2.0 * p1;
                double p  = sqrt(p2 / 6.0);
                double ip = 1.0 / p;
                double c00 = b00 * ip, c01 = a01 * ip, c02 = a02 * ip;
                double c11 = b11 * ip, c12 = a12 * ip, c22 = b22 * ip;
                double detB = c00 * (c11 * c22 - c12 * c12)
                            - c01 * (c01 * c22 - c12 * c02)
                            + c02 * (c01 * c12 - c11 * c02);
                double r = fmin(1.0, fmax(-1.0, 0.5 * detB));
                double phi = acos(r) / 3.0;
                double lmin = q + 2.0 * p * cos(phi + 2.0943951023931953);
                double r0x = a00 - lmin, r0y = a01,        r0z = a02;
                double r1x = a01,        r1y = a11 - lmin, r1z = a12;
                double r2x = a02,        r2y = a12,        r2z = a22 - lmin;
                double v0x = r0y * r1z - r0z * r1y, v0y = r0z * r1x - r0x * r1z, v0z = r0x * r1y - r0y * r1x;
                double v1x = r0y * r2z - r0z * r2y, v1y = r0z * r2x - r0x * r2z, v1z = r0x * r2y - r0y * r2x;
                double v2x = r1y * r2z - r1z * r2y, v2y = r1z * r2x - r1x * r2z, v2z = r1x * r2y - r1y * r2x;
                double n0 = v0x * v0x + v0y * v0y + v0z * v0z;
                double n1 = v1x * v1x + v1y * v1y + v1z * v1z;
                double n2 = v2x * v2x + v2y * v2y + v2z * v2z;
                double vx, vy, vz, nn;
                if (n0 >= n1 && n0 >= n2)      { vx = v0x; vy = v0y; vz = v0z; nn = n0; }
                else if (n1 >= n2)             { vx = v1x; vy = v1y; vz = v1z; nn = n1; }
                else                           { vx = v2x; vy = v2y; vz = v2z; nn = n2; }
                double inr = (nn > 0.0) ? (1.0 / sqrt(nn)) : 0.0;
                zx = vx * inr; zy = vy * inr; zz = vz * inr;
            }
            double dotz = acc[7] * zx + acc[8] * zy + acc[9] * zz;
            if (dotz > 0.0) { zx = -zx; zy = -zy; zz = -zz; }
            msc[0] = (float)zx; msc[1] = (float)zy; msc[2] = (float)zz;
        }
    }
    __syncwarp();

    {   // pz per neighbor
        float zx = msc[0], zy = msc[1], zz = msc[2];
        for (int i = lane; i < send; i += 32)
            pzv[i] = relx[i] * zx + rely[i] * zy + relz[i] * zz;
    }
    __syncwarp();

    {   // xv accumulation (fp64 warp reduce)
        double zx = msc[0], zy = msc[1], zz = msc[2];
        double sx = 0, sy = 0, sz = 0;
        for (int si = lane; si < NS; si += 32) {
            int j = (si < cnt) ? si : 0;
            double pzd = pzv[j], w = wgt[j];
            double t = (w * w) * (pzd * pzd);
            sx += t * (relx[j] - pzd * zx);
            sy += t * (rely[j] - pzd * zy);
            sz += t * (relz[j] - pzd * zz);
        }
        #pragma unroll
        for (int off = 16; off; off >>= 1) {
            sx += __shfl_down_sync(0xffffffffu, sx, off);
            sy += __shfl_down_sync(0xffffffffu, sy, off);
            sz += __shfl_down_sync(0xffffffffu, sz, off);
        }
        if (lane == 0) {
            double nrm = sqrt(sx * sx + sy * sy + sz * sz);
            double inr = 1.0 / (nrm + 1e-8);
            float xx = (float)(sx * inr), xy = (float)(sy * inr), xz = (float)(sz * inr);
            msc[3] = xx; msc[4] = xy; msc[5] = xz;
            float zx2 = msc[0], zy2 = msc[1], zz2 = msc[2];
            msc[6] = zy2 * xz - zz2 * xy;
            msc[7] = zz2 * xx - zx2 * xz;
            msc[8] = zx2 * xy - zy2 * xx;
        }
    }
    __syncwarp();

    {   // LRF in-plane coords -> write geometry to global
        float xx = msc[3], xy = msc[4], xz = msc[5];
        float yx = msc[6], yy = msc[7], yz = msc[8];
        float* gq = g_geo + goff + (size_t)qi * 192;
        for (int i = lane; i < send; i += 32) {
            float rx = relx[i], ry = rely[i], rz = relz[i];
            gq[i]       = rx * xx + ry * xy + rz * xz;
            gq[64 + i]  = rx * yx + ry * yy + rz * yz;
            gq[128 + i] = pzv[i];
        }
        if (lane == 0) g_cnt[coff + qi] = send;
    }
}

// =============== MLP kernel: pure f32x2 compute (big smem, 2 blocks/SM) ===============
// W3q  : float4 [64][32]   32768 B @ 0
// W2q  : float2 [32][32]    8192 B @ 32768
// h1   : u64 [8][32][10]   20480 B @ 40960
// h2   : u64 [8][64][10]   40960 B @ 61440
// geos : float [8][192]     6144 B @ 102400
#define MLP_SMEM 108544

__global__ void __launch_bounds__(256, 2)
mlp_kernel(const float* __restrict__ w1a, const float* __restrict__ g1a, const float* __restrict__ b1a,
           const float* __restrict__ w1b, const float* __restrict__ g1b, const float* __restrict__ b1b,
           const float* __restrict__ w1c, const float* __restrict__ g1c, const float* __restrict__ b1c,
           const float* __restrict__ w2a, const float* __restrict__ g2a, const float* __restrict__ b2a,
           const float* __restrict__ w2b, const float* __restrict__ g2b, const float* __restrict__ b2b,
           const float* __restrict__ w2c, const float* __restrict__ g2c, const float* __restrict__ b2c)
{
    extern __shared__ unsigned char smraw[];
    float4* W3q = (float4*)smraw;
    float2* W2q = (float2*)(smraw + 32768);
    const int tid  = threadIdx.x;
    const int lane = tid & 31;
    const int wid  = tid >> 5;
    u64*   h1w  = (u64*)(smraw + 40960 + wid * 2560);
    u64*   h2w  = (u64*)(smraw + 61440 + wid * 5120);
    float* geos = (float*)(smraw + 102400) + wid * 192;
    const float4* la4 = (const float4*)geos;          // la quads
    const float4* lb4 = (const float4*)(geos + 64);   // lb quads
    const float4* pz4 = (const float4*)(geos + 128);  // pz quads

    const bool sc2 = blockIdx.x < 1024;
    const float* W1  = sc2 ? w2a : w1a;  const float* G1 = sc2 ? g2a : g1a;  const float* B1 = sc2 ? b2a : b1a;
    const float* W2  = sc2 ? w2b : w1b;  const float* G2 = sc2 ? g2b : g1b;  const float* B2 = sc2 ? b2b : b1b;
    const float* W3L = sc2 ? w2c : w1c;  const float* G3 = sc2 ? g2c : g1c;  const float* B3 = sc2 ? b2c : b1c;
    float* fout = sc2 ? g_f2 : g_f1;
    const int goff = sc2 ? 0 : NQ * 192;
    const int coff = sc2 ? 0 : NQ;

    // stage weights
    for (int i = tid; i < 64 * 32; i += 256) {
        int k = i >> 5, l = i & 31;
        W3q[k * 32 + l] = make_float4(W3L[l * 64 + k], W3L[(l + 32) * 64 + k],
                                      W3L[(l + 64) * 64 + k], W3L[(l + 96) * 64 + k]);
    }
    for (int i = tid; i < 32 * 32; i += 256) {
        int k = i >> 5, l = i & 31;
        W2q[k * 32 + l] = make_float2(W2[l * 32 + k], W2[(l + 32) * 32 + k]);
    }

    const int qi = (blockIdx.x & 1023) * 8 + wid;
    const int send = g_cnt[coff + qi];

    // preload geometry for this query
    {
        const float* gq = g_geo + goff + (size_t)qi * 192;
        for (int i = lane; i < 192; i += 32) geos[i] = gq[i];
    }
    __syncthreads();   // weights staged (also covers geos)

    const float bns = 0.99999500003749968752f;  // 1/sqrt(1+1e-5)
    const float wa0 = W1[lane * 3 + 0], wa1 = W1[lane * 3 + 1], wa2 = W1[lane * 3 + 2];
    const float s1  = G1[lane] * bns,  b1v = B1[lane];

    float fm[4] = {0.f, 0.f, 0.f, 0.f};

    for (int s0 = 0; s0 < send; s0 += 16) {
        const int npair = (send - s0 >= 16) ? 8 : 4;
        const int q0 = s0 >> 2;               // quad index base

        // layer 1: 4 neighbors per step via float4 broadcasts, STS.128 store
        for (int pp = 0; pp < (npair >> 1); pp++) {
            float4 a = la4[q0 + pp];
            float4 bq = lb4[q0 + pp];
            float4 c = pz4[q0 + pp];
            float v0 = fmaxf(fmaf(fmaf(wa0, a.x, fmaf(wa1, bq.x, wa2 * c.x)), s1, b1v), 0.f);
            float v1 = fmaxf(fmaf(fmaf(wa0, a.y, fmaf(wa1, bq.y, wa2 * c.y)), s1, b1v), 0.f);
            float v2 = fmaxf(fmaf(fmaf(wa0, a.z, fmaf(wa1, bq.z, wa2 * c.z)), s1, b1v), 0.f);
            float v3 = fmaxf(fmaf(fmaf(wa0, a.w, fmaf(wa1, bq.w, wa2 * c.w)), s1, b1v), 0.f);
            ulonglong2 st;
            st.x = pack2(v0, v1);
            st.y = pack2(v2, v3);
            *(ulonglong2*)&h1w[lane * 10 + 2 * pp] = st;
        }
        __syncwarp();

        // layer 2: 32 -> 64
        {
            u64 acc2[16];
            #pragma unroll
            for (int i = 0; i < 16; i++) acc2[i] = 0;
            if (npair == 8) {
                #pragma unroll 4
                for (int k = 0; k < 32; k++) {
                    float2 w = W2q[k * 32 + lane];
                    u64 wA = pack2(w.x), wB = pack2(w.y);
                    ulonglong2 t01 = *(const ulonglong2*)&h1w[k * 10];
                    ulonglong2 t23 = *(const ulonglong2*)&h1w[k * 10 + 2];
                    ulonglong2 t45 = *(const ulonglong2*)&h1w[k * 10 + 4];
                    ulonglong2 t67 = *(const ulonglong2*)&h1w[k * 10 + 6];
                    u64 hh[8] = {t01.x, t01.y, t23.x, t23.y, t45.x, t45.y, t67.x, t67.y};
                    #pragma unroll
                    for (int p = 0; p < 8; p++) { ffma2(acc2[p], wA, hh[p]); ffma2(acc2[8 + p], wB, hh[p]); }
                }
            } else {
                #pragma unroll 4
                for (int k = 0; k < 32; k++) {
                    float2 w = W2q[k * 32 + lane];
                    u64 wA = pack2(w.x), wB = pack2(w.y);
                    ulonglong2 t01 = *(const ulonglong2*)&h1w[k * 10];
                    ulonglong2 t23 = *(const ulonglong2*)&h1w[k * 10 + 2];
                    u64 hh[4] = {t01.x, t01.y, t23.x, t23.y};
                    #pragma unroll
                    for (int p = 0; p < 4; p++) { ffma2(acc2[p], wA, hh[p]); ffma2(acc2[8 + p], wB, hh[p]); }
                }
            }
            u64 sA = pack2(G2[lane] * bns),      bA = pack2(B2[lane]);
            u64 sB = pack2(G2[lane + 32] * bns), bB = pack2(B2[lane + 32]);
            for (int pp = 0; pp < (npair >> 1); pp++) {
                ulonglong2 stA, stB;
                stA.x = relu2(ffma2c(acc2[2 * pp],     sA, bA));
                stA.y = relu2(ffma2c(acc2[2 * pp + 1], sA, bA));
                stB.x = relu2(ffma2c(acc2[8 + 2 * pp],     sB, bB));
                stB.y = relu2(ffma2c(acc2[8 + 2 * pp + 1], sB, bB));
                *(ulonglong2*)&h2w[lane * 10 + 2 * pp] = stA;
                *(ulonglong2*)&h2w[(lane + 32) * 10 + 2 * pp] = stB;
            }
        }
        __syncwarp();

        // layer 3: 64 -> 128, single pass, 4 out-groups
        {
            u64 acc3[32];
            #pragma unroll
            for (int i = 0; i < 32; i++) acc3[i] = 0;
            if (npair == 8) {
                #pragma unroll 8
                for (int k = 0; k < 64; k++) {
                    float4 w4 = W3q[k * 32 + lane];
                    u64 wp0 = pack2(w4.x), wp1 = pack2(w4.y), wp2 = pack2(w4.z), wp3 = pack2(w4.w);
                    ulonglong2 t01 = *(const ulonglong2*)&h2w[k * 10];
                    ulonglong2 t23 = *(const ulonglong2*)&h2w[k * 10 + 2];
                    ulonglong2 t45 = *(const ulonglong2*)&h2w[k * 10 + 4];
                    ulonglong2 t67 = *(const ulonglong2*)&h2w[k * 10 + 6];
                    u64 hh[8] = {t01.x, t01.y, t23.x, t23.y, t45.x, t45.y, t67.x, t67.y};
                    #pragma unroll
                    for (int p = 0; p < 8; p++) {
                        ffma2(acc3[p],      wp0, hh[p]);
                        ffma2(acc3[8 + p],  wp1, hh[p]);
                        ffma2(acc3[16 + p], wp2, hh[p]);
                        ffma2(acc3[24 + p], wp3, hh[p]);
                    }
                }
            } else {
                #pragma unroll 4
                for (int k = 0; k < 64; k++) {
                    float4 w4 = W3q[k * 32 + lane];
                    u64 wp0 = pack2(w4.x), wp1 = pack2(w4.y), wp2 = pack2(w4.z), wp3 = pack2(w4.w);
                    ulonglong2 t01 = *(const ulonglong2*)&h2w[k * 10];
                    ulonglong2 t23 = *(const ulonglong2*)&h2w[k * 10 + 2];
                    u64 hh[4] = {t01.x, t01.y, t23.x, t23.y};
                    #pragma unroll
                    for (int p = 0; p < 4; p++) {
                        ffma2(acc3[p],      wp0, hh[p]);
                        ffma2(acc3[8 + p],  wp1, hh[p]);
                        ffma2(acc3[16 + p], wp2, hh[p]);
                        ffma2(acc3[24 + p], wp3, hh[p]);
                    }
                }
            }
            #pragma unroll
            for (int j = 0; j < 4; j++) {
                u64 s3 = pack2(G3[lane + 32 * j] * bns), b3 = pack2(B3[lane + 32 * j]);
                for (int p = 0; p < npair; p++) {
                    u64 t = ffma2c(acc3[j * 8 + p], s3, b3);
                    float x, y; unpack2(t, x, y);
                    fm[j] = fmaxf(fm[j], fmaxf(x, y));
                }
            }
        }
        __syncwarp();
    }

    #pragma unroll
    for (int j = 0; j < 4; j++)
        fout[(size_t)qi * 128 + lane + 32 * j] = fm[j];
}

// ---------------- final linear: full-W3t staging, one barrier ----------------
// fp : u64  [32 pairs][256 c]   65536 B @ 0
// wt : float [256][128]        131072 B @ 65536
#define FINAL_SMEM (65536 + 131072)   // 196608

__global__ void __launch_bounds__(512)
final_kernel(const float* __restrict__ B3f, float* __restrict__ out)
{
    extern __shared__ unsigned char fraw[];
    u64*   fp = (u64*)fraw;             // [pair][256]
    float* wt = (float*)(fraw + 65536); // [256][128]
    const int tid = threadIdx.x, lane = tid & 31, wid = tid >> 5;
    const int q0 = blockIdx.x * 64;

    // stage full W3t (float4 loads)
    {
        const float4* src = (const float4*)g_W3t;
        float4* dst = (float4*)wt;
        for (int i = tid; i < 256 * 32; i += 512) dst[i] = src[i];
    }
    // stage packed feature pairs: fp[pr][c] = (feat[q0+2pr][c], feat[q0+2pr+1][c])
    for (int i = tid; i < 32 * 128; i += 512) {
        int pr = i >> 7, c = i & 127;
        size_t ra = (size_t)(q0 + 2 * pr) * 128 + c;
        size_t rb = (size_t)(q0 + 2 * pr + 1) * 128 + c;
        fp[pr * 256 + c]       = pack2(g_f1[ra], g_f1[rb]);
        fp[pr * 256 + 128 + c] = pack2(g_f2[ra], g_f2[rb]);
    }
    __syncthreads();

    u64 acc[2][4];   // [local pair][output group]
    #pragma unroll
    for (int pr = 0; pr < 2; pr++)
        #pragma unroll
        for (int j = 0; j < 4; j++) acc[pr][j] = 0;

    const int prbase = wid * 2;   // 2 pairs (4 queries) per warp
    #pragma unroll 8
    for (int c = 0; c < 256; c++) {
        const float* wr = wt + c * 128;
        u64 wp0 = pack2(wr[lane]);
        u64 wp1 = pack2(wr[lane + 32]);
        u64 wp2 = pack2(wr[lane + 64]);
        u64 wp3 = pack2(wr[lane + 96]);
        #pragma unroll
        for (int pr = 0; pr < 2; pr++) {
            u64 f = fp[(prbase + pr) * 256 + c];
            ffma2(acc[pr][0], wp0, f);
            ffma2(acc[pr][1], wp1, f);
            ffma2(acc[pr][2], wp2, f);
            ffma2(acc[pr][3], wp3, f);
        }
    }
    #pragma unroll
    for (int pr = 0; pr < 2; pr++) {
        int qa = q0 + 2 * (prbase + pr);
        #pragma unroll
        for (int j = 0; j < 4; j++) {
            float x, y; unpack2(acc[pr][j], x, y);
            float bb = B3f[lane + 32 * j];
            out[(size_t)qa * 128 + lane + 32 * j]       = x + bb;
            out[(size_t)(qa + 1) * 128 + lane + 32 * j] = y + bb;
        }
    }
}

extern "C" void kernel_launch(void* const* d_in, const int* in_sizes, int n_in,
                              void* d_out, int out_size)
{
    const float* pts  = (const float*)d_in[0];
    const float* w1a  = (const float*)d_in[1];
    const float* g1a  = (const float*)d_in[2];
    const float* bb1a = (const float*)d_in[3];
    const float* w1b  = (const float*)d_in[4];
    const float* g1b  = (const float*)d_in[5];
    const float* bb1b = (const float*)d_in[6];
    const float* w1c  = (const float*)d_in[7];
    const float* g1c  = (const float*)d_in[8];
    const float* bb1c = (const float*)d_in[9];
    const float* w2a  = (const float*)d_in[10];
    const float* g2a  = (const float*)d_in[11];
    const float* bb2a = (const float*)d_in[12];
    const float* w2b  = (const float*)d_in[13];
    const float* g2b  = (const float*)d_in[14];
    const float* bb2b = (const float*)d_in[15];
    const float* w2c  = (const float*)d_in[16];
    const float* g2c  = (const float*)d_in[17];
    const float* bb2c = (const float*)d_in[18];
    const float* w3   = (const float*)d_in[19];
    const float* b3   = (const float*)d_in[20];

    cudaFuncSetAttribute(mlp_kernel, cudaFuncAttributeMaxDynamicSharedMemorySize, MLP_SMEM);
    cudaFuncSetAttribute(final_kernel, cudaFuncAttributeMaxDynamicSharedMemorySize, FINAL_SMEM);

    prep_kernel<<<128, 256>>>(pts, w3);
    geom_kernel<<<2048, 256>>>();
    mlp_kernel<<<2048, 256, MLP_SMEM>>>(w1a, g1a, bb1a, w1b, g1b, bb1b, w1c, g1c, bb1c,
                                        w2a, g2a, bb2a, w2b, g2b, bb2b, w2c, g2c, bb2c);
    final_kernel<<<NQ / 64, 512, FINAL_SMEM>>>(b3, (float*)d_out);
}

// round 16
// speedup vs baseline: 1.1650x; 1.0247x over previous
#include <cuda_runtime.h>
#include <math.h>

#define BATCH 2
#define NPTS  4096
#define MQ    4096
#define NQ    (BATCH * MQ)

// scratch
__device__ float  g_f1[NQ * 128];
__device__ float  g_f2[NQ * 128];
__device__ float4 g_p4[BATCH * NPTS];   // (x, y, z, 0) packed points
__device__ float  g_W3t[256 * 128];     // transposed final weights [c][o]
__device__ float  g_geo[2 * NQ * 192];  // per scale, per query: la[64] lb[64] pz[64]
__device__ int    g_cnt[2 * NQ];        // send counts (multiple of 4)

// ---------------- f32x2 helpers ----------------
typedef unsigned long long u64;
__device__ __forceinline__ u64 pack2(float x) {
    u64 r; asm("mov.b64 %0, {%1,%1};" : "=l"(r) : "f"(x)); return r;
}
__device__ __forceinline__ u64 pack2(float x, float y) {
    u64 r; asm("mov.b64 %0, {%1,%2};" : "=l"(r) : "f"(x), "f"(y)); return r;
}
__device__ __forceinline__ void unpack2(u64 v, float& x, float& y) {
    asm("mov.b64 {%0,%1}, %2;" : "=f"(x), "=f"(y) : "l"(v));
}
__device__ __forceinline__ void ffma2(u64& d, u64 a, u64 b) {
    asm("fma.rn.f32x2 %0, %1, %2, %0;" : "+l"(d) : "l"(a), "l"(b));
}
__device__ __forceinline__ u64 ffma2c(u64 a, u64 b, u64 c) {
    u64 d; asm("fma.rn.f32x2 %0, %1, %2, %3;" : "=l"(d) : "l"(a), "l"(b), "l"(c)); return d;
}
__device__ __forceinline__ u64 relu2(u64 v) {
    float x, y; unpack2(v, x, y);
    return pack2(fmaxf(x, 0.f), fmaxf(y, 0.f));
}

// =============== prep: pack points to float4 + transpose final weights ===============
__global__ void prep_kernel(const float* __restrict__ pts, const float* __restrict__ w3)
{
    int i = blockIdx.x * blockDim.x + threadIdx.x;   // 0..32767
    if (i < BATCH * NPTS) {
        float x = pts[i * 3 + 0], y = pts[i * 3 + 1], z = pts[i * 3 + 2];
        g_p4[i] = make_float4(x, y, z, 0.0f);
    }
    if (i < 128 * 256) {
        int o = i >> 8, c = i & 255;
        g_W3t[c * 128 + o] = w3[i];
    }
}

// =============== geometry kernel: ball query + LRF (low smem, high occ) ===============
__global__ void __launch_bounds__(256)
geom_kernel()
{
    __shared__ float sm[8][352];
    const int tid  = threadIdx.x;
    const int lane = tid & 31;
    const int wid  = tid >> 5;
    float* wr   = sm[wid];
    float* relx = wr;        float* rely = wr + 64;  float* relz = wr + 128;
    float* wgt  = wr + 192;  float* pzv  = wr + 256; float* msc  = wr + 320;

    const bool sc2 = blockIdx.x < 1024;
    const float radius = sc2 ? 0.2f : 0.1f;
    const int   NS     = sc2 ? 64 : 32;
    const int   goff   = sc2 ? 0 : NQ * 192;
    const int   coff   = sc2 ? 0 : NQ;

    const int qi = (blockIdx.x & 1023) * 8 + wid;
    const int b  = qi >> 12;
    const int m  = qi & (MQ - 1);
    const float4* p4 = g_p4 + b * NPTS;
    const float4 q4 = p4[m];
    const float qx = q4.x, qy = q4.y, qz = q4.z;
    const float r2 = radius * radius;
    const unsigned lmask = (1u << lane) - 1u;

    // warp-synchronous ball query: 64 points per iteration (2 float4 per lane)
    int cnt = 0;
    for (int c = 0; c < NPTS && cnt < NS; c += 64) {
        int i0 = c + 2 * lane;
        float4 p0 = p4[i0], p1 = p4[i0 + 1];
        float dx0 = p0.x - qx, dy0 = p0.y - qy, dz0 = p0.z - qz;
        float dx1 = p1.x - qx, dy1 = p1.y - qy, dz1 = p1.z - qz;
        float d20 = dx0 * dx0 + dy0 * dy0 + dz0 * dz0;
        float d21 = dx1 * dx1 + dy1 * dy1 + dz1 * dz1;
        bool pr0 = d20 < r2, pr1 = d21 < r2;
        unsigned b0 = __ballot_sync(0xffffffffu, pr0);
        unsigned b1 = __ballot_sync(0xffffffffu, pr1);
        int before = cnt + __popc(b0 & lmask) + __popc(b1 & lmask);
        int pos0 = before;
        int pos1 = before + (pr0 ? 1 : 0);
        if (pr0 && pos0 < NS) {
            relx[pos0] = dx0; rely[pos0] = dy0; relz[pos0] = dz0;
            wgt[pos0]  = fmaxf(radius - sqrtf(d20), 0.0f);
        }
        if (pr1 && pos1 < NS) {
            relx[pos1] = dx1; rely[pos1] = dy1; relz[pos1] = dz1;
            wgt[pos1]  = fmaxf(radius - sqrtf(d21), 0.0f);
        }
        cnt += __popc(b0) + __popc(b1);
    }
    cnt = min(cnt, NS);
    __syncwarp();
    // quad-granularity padding: duplicates beyond cnt cannot change max-pool
    const int send = min(NS, (cnt + 3) & ~3);
    {
        float r0x = relx[0], r0y = rely[0], r0z = relz[0], w0 = wgt[0];
        for (int i = cnt + lane; i < send; i += 32) {
            relx[i] = r0x; rely[i] = r0y; relz[i] = r0z; wgt[i] = w0;
        }
    }
    __syncwarp();

    // weighted covariance + Σrel (fp64 warp reduce)
    {
        double acc[10];
        #pragma unroll
        for (int i = 0; i < 10; i++) acc[i] = 0.0;
        for (int si = lane; si < NS; si += 32) {
            int j = (si < cnt) ? si : 0;    // replicate-first semantics
            double rx = relx[j], ry = rely[j], rz = relz[j], w = wgt[j];
            acc[0] += w * rx * rx; acc[1] += w * rx * ry; acc[2] += w * rx * rz;
            acc[3] += w * ry * ry; acc[4] += w * ry * rz; acc[5] += w * rz * rz;
            acc[6] += w; acc[7] += rx; acc[8] += ry; acc[9] += rz;
        }
        #pragma unroll
        for (int off = 16; off; off >>= 1) {
            #pragma unroll
            for (int i = 0; i < 10; i++) acc[i] += __shfl_down_sync(0xffffffffu, acc[i], off);
        }
        if (lane == 0) {
            double inv = 1.0 / (acc[6] + 1e-8);
            double a00 = acc[0] * inv, a01 = acc[1] * inv, a02 = acc[2] * inv;
            double a11 = acc[3] * inv, a12 = acc[4] * inv, a22 = acc[5] * inv;
            double zx, zy, zz;
            double p1 = a01 * a01 + a02 * a02 + a12 * a12;
            if (p1 < 1e-30) {
                if (a00 <= a11 && a00 <= a22)      { zx = 1; zy = 0; zz = 0; }
                else if (a11 <= a22)               { zx = 0; zy = 1; zz = 0; }
                else                               { zx = 0; zy = 0; zz = 1; }
            } else {
                double q  = (a00 + a11 + a22) / 3.0;
                double b00 = a00 - q, b11 = a11 - q, b22 = a22 - q;
                double p2 = b00 * b00 + b11 * b11 + b22 * b22 + 2.0 * p1;
                double p  = sqrt(p2 / 6.0);
                double ip = 1.0 / p;
                double c00 = b00 * ip, c01 = a01 * ip, c02 = a02 * ip;
                double c11 = b11 * ip, c12 = a12 * ip, c22 = b22 * ip;
                double detB = c00 * (c11 * c22 - c12 * c12)
                            - c01 * (c01 * c22 - c12 * c02)
                            + c02 * (c01 * c12 - c11 * c02);
                double r = fmin(1.0, fmax(-1.0, 0.5 * detB));
                double phi = acos(r) / 3.0;
                double lmin = q + 2.0 * p * cos(phi + 2.0943951023931953);
                double r0x = a00 - lmin, r0y = a01,        r0z = a02;
                double r1x = a01,        r1y = a11 - lmin, r1z = a12;
                double r2x = a02,        r2y = a12,        r2z = a22 - lmin;
                double v0x = r0y * r1z - r0z * r1y, v0y = r0z * r1x - r0x * r1z, v0z = r0x * r1y - r0y * r1x;
                double v1x = r0y * r2z - r0z * r2y, v1y = r0z * r2x - r0x * r2z, v1z = r0x * r2y - r0y * r2x;
                double v2x = r1y * r2z - r1z * r2y, v2y = r1z * r2x - r1x * r2z, v2z = r1x * r2y - r1y * r2x;
                double n0 = v0x * v0x + v0y * v0y + v0z * v0z;
                double n1 = v1x * v1x + v1y * v1y + v1z * v1z;
                double n2 = v2x * v2x + v2y * v2y + v2z * v2z;
                double vx, vy, vz, nn;
                if (n0 >= n1 && n0 >= n2)      { vx = v0x; vy = v0y; vz = v0z; nn = n0; }
                else if (n1 >= n2)             { vx = v1x; vy = v1y; vz = v1z; nn = n1; }
                else                           { vx = v2x; vy = v2y; vz = v2z; nn = n2; }
                double inr = (nn > 0.0) ? (1.0 / sqrt(nn)) : 0.0;
                zx = vx * inr; zy = vy * inr; zz = vz * inr;
            }
            double dotz = acc[7] * zx + acc[8] * zy + acc[9] * zz;
            if (dotz > 0.0) { zx = -zx; zy = -zy; zz = -zz; }
            msc[0] = (float)zx; msc[1] = (float)zy; msc[2] = (float)zz;
        }
    }
    __syncwarp();

    {   // pz per neighbor
        float zx = msc[0], zy = msc[1], zz = msc[2];
        for (int i = lane; i < send; i += 32)
            pzv[i] = relx[i] * zx + rely[i] * zy + relz[i] * zz;
    }
    __syncwarp();

    {   // xv accumulation (fp64 warp reduce)
        double zx = msc[0], zy = msc[1], zz = msc[2];
        double sx = 0, sy = 0, sz = 0;
        for (int si = lane; si < NS; si += 32) {
            int j = (si < cnt) ? si : 0;
            double pzd = pzv[j], w = wgt[j];
            double t = (w * w) * (pzd * pzd);
            sx += t * (relx[j] - pzd * zx);
            sy += t * (rely[j] - pzd * zy);
            sz += t * (relz[j] - pzd * zz);
        }
        #pragma unroll
        for (int off = 16; off; off >>= 1) {
            sx += __shfl_down_sync(0xffffffffu, sx, off);
            sy += __shfl_down_sync(0xffffffffu, sy, off);
            sz += __shfl_down_sync(0xffffffffu, sz, off);
        }
        if (lane == 0) {
            double nrm = sqrt(sx * sx + sy * sy + sz * sz);
            double inr = 1.0 / (nrm + 1e-8);
            float xx = (float)(sx * inr), xy = (float)(sy * inr), xz = (float)(sz * inr);
            msc[3] = xx; msc[4] = xy; msc[5] = xz;
            float zx2 = msc[0], zy2 = msc[1], zz2 = msc[2];
            msc[6] = zy2 * xz - zz2 * xy;
            msc[7] = zz2 * xx - zx2 * xz;
            msc[8] = zx2 * xy - zy2 * xx;
        }
    }
    __syncwarp();

    {   // LRF in-plane coords -> write geometry to global
        float xx = msc[3], xy = msc[4], xz = msc[5];
        float yx = msc[6], yy = msc[7], yz = msc[8];
        float* gq = g_geo + goff + (size_t)qi * 192;
        for (int i = lane; i < send; i += 32) {
            float rx = relx[i], ry = rely[i], rz = relz[i];
            gq[i]       = rx * xx + ry * xy + rz * xz;
            gq[64 + i]  = rx * yx + ry * yy + rz * yz;
            gq[128 + i] = pzv[i];
        }
        if (lane == 0) g_cnt[coff + qi] = send;
    }
}

// =============== MLP chunk: static NPAIR body (NPAIR in {2,4,8}) ===============
template <int NPAIR>
__device__ __forceinline__ void mlp_chunk(
    int lane, int q0,
    const float4* la4, const float4* lb4, const float4* pz4,
    u64* h1w, u64* h2w, const float2* W2q, const float4* W3q,
    float wa0, float wa1, float wa2, float s1, float b1v,
    const float* G2, const float* B2, const float* G3, const float* B3,
    float bns, float* fm)
{
    constexpr int NQUAD = NPAIR / 2;

    // layer 1: per-quad float4 broadcasts, STS.128 store
    #pragma unroll
    for (int pp = 0; pp < NQUAD; pp++) {
        float4 a = la4[q0 + pp];
        float4 bq = lb4[q0 + pp];
        float4 c = pz4[q0 + pp];
        float v0 = fmaxf(fmaf(fmaf(wa0, a.x, fmaf(wa1, bq.x, wa2 * c.x)), s1, b1v), 0.f);
        float v1 = fmaxf(fmaf(fmaf(wa0, a.y, fmaf(wa1, bq.y, wa2 * c.y)), s1, b1v), 0.f);
        float v2 = fmaxf(fmaf(fmaf(wa0, a.z, fmaf(wa1, bq.z, wa2 * c.z)), s1, b1v), 0.f);
        float v3 = fmaxf(fmaf(fmaf(wa0, a.w, fmaf(wa1, bq.w, wa2 * c.w)), s1, b1v), 0.f);
        ulonglong2 st;
        st.x = pack2(v0, v1);
        st.y = pack2(v2, v3);
        *(ulonglong2*)&h1w[lane * 10 + 2 * pp] = st;
    }
    __syncwarp();

    // layer 2: 32 -> 64, out channels (lane, lane+32)
    {
        u64 acc2[2 * NPAIR];
        #pragma unroll
        for (int i = 0; i < 2 * NPAIR; i++) acc2[i] = 0;
        #pragma unroll 4
        for (int k = 0; k < 32; k++) {
            float2 w = W2q[k * 32 + lane];
            u64 wA = pack2(w.x), wB = pack2(w.y);
            u64 hh[NPAIR];
            #pragma unroll
            for (int pp = 0; pp < NQUAD; pp++) {
                ulonglong2 t = *(const ulonglong2*)&h1w[k * 10 + 2 * pp];
                hh[2 * pp] = t.x; hh[2 * pp + 1] = t.y;
            }
            #pragma unroll
            for (int p = 0; p < NPAIR; p++) { ffma2(acc2[p], wA, hh[p]); ffma2(acc2[NPAIR + p], wB, hh[p]); }
        }
        u64 sA = pack2(G2[lane] * bns),      bA = pack2(B2[lane]);
        u64 sB = pack2(G2[lane + 32] * bns), bB = pack2(B2[lane + 32]);
        #pragma unroll
        for (int pp = 0; pp < NQUAD; pp++) {
            ulonglong2 stA, stB;
            stA.x = relu2(ffma2c(acc2[2 * pp],     sA, bA));
            stA.y = relu2(ffma2c(acc2[2 * pp + 1], sA, bA));
            stB.x = relu2(ffma2c(acc2[NPAIR + 2 * pp],     sB, bB));
            stB.y = relu2(ffma2c(acc2[NPAIR + 2 * pp + 1], sB, bB));
            *(ulonglong2*)&h2w[lane * 10 + 2 * pp] = stA;
            *(ulonglong2*)&h2w[(lane + 32) * 10 + 2 * pp] = stB;
        }
    }
    __syncwarp();

    // layer 3: 64 -> 128, single pass, 4 out-groups
    {
        u64 acc3[4 * NPAIR];
        #pragma unroll
        for (int i = 0; i < 4 * NPAIR; i++) acc3[i] = 0;
        #pragma unroll 8
        for (int k = 0; k < 64; k++) {
            float4 w4 = W3q[k * 32 + lane];
            u64 wp0 = pack2(w4.x), wp1 = pack2(w4.y), wp2 = pack2(w4.z), wp3 = pack2(w4.w);
            u64 hh[NPAIR];
            #pragma unroll
            for (int pp = 0; pp < NQUAD; pp++) {
                ulonglong2 t = *(const ulonglong2*)&h2w[k * 10 + 2 * pp];
                hh[2 * pp] = t.x; hh[2 * pp + 1] = t.y;
            }
            #pragma unroll
            for (int p = 0; p < NPAIR; p++) {
                ffma2(acc3[p],             wp0, hh[p]);
                ffma2(acc3[NPAIR + p],     wp1, hh[p]);
                ffma2(acc3[2 * NPAIR + p], wp2, hh[p]);
                ffma2(acc3[3 * NPAIR + p], wp3, hh[p]);
            }
        }
        #pragma unroll
        for (int j = 0; j < 4; j++) {
            u64 s3 = pack2(G3[lane + 32 * j] * bns), b3 = pack2(B3[lane + 32 * j]);
            #pragma unroll
            for (int p = 0; p < NPAIR; p++) {
                u64 t = ffma2c(acc3[j * NPAIR + p], s3, b3);
                float x, y; unpack2(t, x, y);
                fm[j] = fmaxf(fm[j], fmaxf(x, y));
            }
        }
    }
    __syncwarp();
}

// =============== MLP kernel: pure f32x2 compute (big smem, 2 blocks/SM) ===============
// W3q  : float4 [64][32]   32768 B @ 0
// W2q  : float2 [32][32]    8192 B @ 32768
// h1   : u64 [8][32][10]   20480 B @ 40960
// h2   : u64 [8][64][10]   40960 B @ 61440
// geos : float [8][192]     6144 B @ 102400
#define MLP_SMEM 108544

__global__ void __launch_bounds__(256, 2)
mlp_kernel(const float* __restrict__ w1a, const float* __restrict__ g1a, const float* __restrict__ b1a,
           const float* __restrict__ w1b, const float* __restrict__ g1b, const float* __restrict__ b1b,
           const float* __restrict__ w1c, const float* __restrict__ g1c, const float* __restrict__ b1c,
           const float* __restrict__ w2a, const float* __restrict__ g2a, const float* __restrict__ b2a,
           const float* __restrict__ w2b, const float* __restrict__ g2b, const float* __restrict__ b2b,
           const float* __restrict__ w2c, const float* __restrict__ g2c, const float* __restrict__ b2c)
{
    extern __shared__ unsigned char smraw[];
    float4* W3q = (float4*)smraw;
    float2* W2q = (float2*)(smraw + 32768);
    const int tid  = threadIdx.x;
    const int lane = tid & 31;
    const int wid  = tid >> 5;
    u64*   h1w  = (u64*)(smraw + 40960 + wid * 2560);
    u64*   h2w  = (u64*)(smraw + 61440 + wid * 5120);
    float* geos = (float*)(smraw + 102400) + wid * 192;
    const float4* la4 = (const float4*)geos;          // la quads
    const float4* lb4 = (const float4*)(geos + 64);   // lb quads
    const float4* pz4 = (const float4*)(geos + 128);  // pz quads

    const bool sc2 = blockIdx.x < 1024;
    const float* W1  = sc2 ? w2a : w1a;  const float* G1 = sc2 ? g2a : g1a;  const float* B1 = sc2 ? b2a : b1a;
    const float* W2  = sc2 ? w2b : w1b;  const float* G2 = sc2 ? g2b : g1b;  const float* B2 = sc2 ? b2b : b1b;
    const float* W3L = sc2 ? w2c : w1c;  const float* G3 = sc2 ? g2c : g1c;  const float* B3 = sc2 ? b2c : b1c;
    float* fout = sc2 ? g_f2 : g_f1;
    const int goff = sc2 ? 0 : NQ * 192;
    const int coff = sc2 ? 0 : NQ;

    // stage weights
    for (int i = tid; i < 64 * 32; i += 256) {
        int k = i >> 5, l = i & 31;
        W3q[k * 32 + l] = make_float4(W3L[l * 64 + k], W3L[(l + 32) * 64 + k],
                                      W3L[(l + 64) * 64 + k], W3L[(l + 96) * 64 + k]);
    }
    for (int i = tid; i < 32 * 32; i += 256) {
        int k = i >> 5, l = i & 31;
        W2q[k * 32 + l] = make_float2(W2[l * 32 + k], W2[(l + 32) * 32 + k]);
    }

    const int qi = (blockIdx.x & 1023) * 8 + wid;
    const int send = g_cnt[coff + qi];   // multiple of 4

    // preload geometry for this query
    {
        const float* gq = g_geo + goff + (size_t)qi * 192;
        for (int i = lane; i < 192; i += 32) geos[i] = gq[i];
    }
    __syncthreads();   // weights staged (also covers geos)

    const float bns = 0.99999500003749968752f;  // 1/sqrt(1+1e-5)
    const float wa0 = W1[lane * 3 + 0], wa1 = W1[lane * 3 + 1], wa2 = W1[lane * 3 + 2];
    const float s1  = G1[lane] * bns,  b1v = B1[lane];

    float fm[4] = {0.f, 0.f, 0.f, 0.f};

    int s0 = 0;
    while (send - s0 >= 16) {
        mlp_chunk<8>(lane, s0 >> 2, la4, lb4, pz4, h1w, h2w, W2q, W3q,
                     wa0, wa1, wa2, s1, b1v, G2, B2, G3, B3, bns, fm);
        s0 += 16;
    }
    if (send - s0 >= 8) {
        mlp_chunk<4>(lane, s0 >> 2, la4, lb4, pz4, h1w, h2w, W2q, W3q,
                     wa0, wa1, wa2, s1, b1v, G2, B2, G3, B3, bns, fm);
        s0 += 8;
    }
    if (send - s0 >= 4) {
        mlp_chunk<2>(lane, s0 >> 2, la4, lb4, pz4, h1w, h2w, W2q, W3q,
                     wa0, wa1, wa2, s1, b1v, G2, B2, G3, B3, bns, fm);
        s0 += 4;
    }

    #pragma unroll
    for (int j = 0; j < 4; j++)
        fout[(size_t)qi * 128 + lane + 32 * j] = fm[j];
}

// ---------------- final linear: full-W3t staging, one barrier ----------------
// fp : u64  [32 pairs][256 c]   65536 B @ 0
// wt : float [256][128]        131072 B @ 65536
#define FINAL_SMEM (65536 + 131072)   // 196608

__global__ void __launch_bounds__(512)
final_kernel(const float* __restrict__ B3f, float* __restrict__ out)
{
    extern __shared__ unsigned char fraw[];
    u64*   fp = (u64*)fraw;             // [pair][256]
    float* wt = (float*)(fraw + 65536); // [256][128]
    const int tid = threadIdx.x, lane = tid & 31, wid = tid >> 5;
    const int q0 = blockIdx.x * 64;

    // stage full W3t (float4 loads)
    {
        const float4* src = (const float4*)g_W3t;
        float4* dst = (float4*)wt;
        for (int i = tid; i < 256 * 32; i += 512) dst[i] = src[i];
    }
    // stage packed feature pairs: fp[pr][c] = (feat[q0+2pr][c], feat[q0+2pr+1][c])
    for (int i = tid; i < 32 * 128; i += 512) {
        int pr = i >> 7, c = i & 127;
        size_t ra = (size_t)(q0 + 2 * pr) * 128 + c;
        size_t rb = (size_t)(q0 + 2 * pr + 1) * 128 + c;
        fp[pr * 256 + c]       = pack2(g_f1[ra], g_f1[rb]);
        fp[pr * 256 + 128 + c] = pack2(g_f2[ra], g_f2[rb]);
    }
    __syncthreads();

    u64 acc[2][4];   // [local pair][output group]
    #pragma unroll
    for (int pr = 0; pr < 2; pr++)
        #pragma unroll
        for (int j = 0; j < 4; j++) acc[pr][j] = 0;

    const int prbase = wid * 2;   // 2 pairs (4 queries) per warp
    #pragma unroll 8
    for (int c = 0; c < 256; c++) {
        const float* wr = wt + c * 128;
        u64 wp0 = pack2(wr[lane]);
        u64 wp1 = pack2(wr[lane + 32]);
        u64 wp2 = pack2(wr[lane + 64]);
        u64 wp3 = pack2(wr[lane + 96]);
        #pragma unroll
        for (int pr = 0; pr < 2; pr++) {
            u64 f = fp[(prbase + pr) * 256 + c];
            ffma2(acc[pr][0], wp0, f);
            ffma2(acc[pr][1], wp1, f);
            ffma2(acc[pr][2], wp2, f);
            ffma2(acc[pr][3], wp3, f);
        }
    }
    #pragma unroll
    for (int pr = 0; pr < 2; pr++) {
        int qa = q0 + 2 * (prbase + pr);
        #pragma unroll
        for (int j = 0; j < 4; j++) {
            float x, y; unpack2(acc[pr][j], x, y);
            float bb = B3f[lane + 32 * j];
            out[(size_t)qa * 128 + lane + 32 * j]       = x + bb;
            out[(size_t)(qa + 1) * 128 + lane + 32 * j] = y + bb;
        }
    }
}

extern "C" void kernel_launch(void* const* d_in, const int* in_sizes, int n_in,
                              void* d_out, int out_size)
{
    const float* pts  = (const float*)d_in[0];
    const float* w1a  = (const float*)d_in[1];
    const float* g1a  = (const float*)d_in[2];
    const float* bb1a = (const float*)d_in[3];
    const float* w1b  = (const float*)d_in[4];
    const float* g1b  = (const float*)d_in[5];
    const float* bb1b = (const float*)d_in[6];
    const float* w1c  = (const float*)d_in[7];
    const float* g1c  = (const float*)d_in[8];
    const float* bb1c = (const float*)d_in[9];
    const float* w2a  = (const float*)d_in[10];
    const float* g2a  = (const float*)d_in[11];
    const float* bb2a = (const float*)d_in[12];
    const float* w2b  = (const float*)d_in[13];
    const float* g2b  = (const float*)d_in[14];
    const float* bb2b = (const float*)d_in[15];
    const float* w2c  = (const float*)d_in[16];
    const float* g2c  = (const float*)d_in[17];
    const float* bb2c = (const float*)d_in[18];
    const float* w3   = (const float*)d_in[19];
    const float* b3   = (const float*)d_in[20];

    cudaFuncSetAttribute(mlp_kernel, cudaFuncAttributeMaxDynamicSharedMemorySize, MLP_SMEM);
    cudaFuncSetAttribute(final_kernel, cudaFuncAttributeMaxDynamicSharedMemorySize, FINAL_SMEM);

    prep_kernel<<<128, 256>>>(pts, w3);
    geom_kernel<<<2048, 256>>>();
    mlp_kernel<<<2048, 256, MLP_SMEM>>>(w1a, g1a, bb1a, w1b, g1b, bb1b, w1c, g1c, bb1c,
                                        w2a, g2a, bb2a, w2b, g2b, bb2b, w2c, g2c, bb2c);
    final_kernel<<<NQ / 64, 512, FINAL_SMEM>>>(b3, (float*)d_out);
}